// round 4
// baseline (speedup 1.0000x reference)
#include <cuda_runtime.h>
#include <cuda_bf16.h>

// ---------------------------------------------------------------------------
// DetectionLoss (YOLOv5-style), two kernels, ZERO global atomics.
//   p3 [16,3,80,80,85] p4 [16,3,40,40,85] p5 [16,3,20,20,85]
//   boxes [16,64,4] xyxy, labels [16,64] i32, valid [16,64] bool, anchors[3,3,2]
// Output: scalar f32.
//
// BCE(x,t) = softplus(x) - x*t  =>
//   obj_l = ( sum_all softplus(x4) - sum_{unique pos cells} x4 ) / Ncells_l
//
// Kernel 1: blocks 0..2 = per-layer positives (smem-hash dedup, results to
//   per-layer global slots); blocks 3..452 = obj softplus sweep, each block
//   covers an exact cell range (no bounds checks), 4 independent loads/thread,
//   block-reduces to g_part[blockIdx.x] (distinct slot -> no atomics, no reset).
// Kernel 2: single block sums the 450 partials + combines pos results.
// All state is overwritten every launch -> graph-replay deterministic.
// ---------------------------------------------------------------------------

#define B_    16
#define M_    64
#define A_    3
#define NC_   80
#define CH_   85
#define NBOX  (B_ * M_)               // 1024
#define CELLS0 (B_ * A_ * 80 * 80)    // 307200
#define CELLS1 (B_ * A_ * 40 * 40)    // 76800
#define CELLS2 (B_ * A_ * 20 * 20)    // 19200

#define TPB 256
#define OBJ_BLK0 (CELLS0 / (TPB * 4))   // 300  (1024 cells/block)
#define OBJ_BLK1 (CELLS1 / (TPB * 4))   // 75   (1024 cells/block)
#define OBJ_BLK2 (CELLS2 / TPB)         // 75   (256 cells/block)
#define OBJ_BLOCKS (OBJ_BLK0 + OBJ_BLK1 + OBJ_BLK2)   // 450
#define TOTAL_BLOCKS (3 + OBJ_BLOCKS)                  // 453
#define HASH_SZ 2048

static __device__ float  g_part[TOTAL_BLOCKS];  // obj partial per block
static __device__ double g_negx[3];             // - sum x4 over unique pos cells
static __device__ double g_cls[3];
static __device__ double g_box[3];
static __device__ int    g_npos[3];

__device__ __forceinline__ float softplusf(float x) {
    return fmaxf(x, 0.0f) + log1pf(expf(-fabsf(x)));
}

// ---------------------------------------------------------------------------
__global__ void __launch_bounds__(TPB)
dl_main_kernel(const float* __restrict__ p3,
               const float* __restrict__ p4,
               const float* __restrict__ p5,
               const float* __restrict__ boxes,
               const int*   __restrict__ labels,
               const unsigned char* __restrict__ valid,
               const float* __restrict__ anchors) {
    const int tid = threadIdx.x;

    if (blockIdx.x >= 3) {
        // ============== obj softplus sweep: exact ranges, no checks =========
        const int o = blockIdx.x - 3;
        float acc;
        if (o < OBJ_BLK0) {
            const long c0 = (long)o * (TPB * 4) + tid;
            float v0 = __ldg(&p3[(c0            ) * CH_ + 4]);
            float v1 = __ldg(&p3[(c0 + TPB      ) * CH_ + 4]);
            float v2 = __ldg(&p3[(c0 + TPB * 2  ) * CH_ + 4]);
            float v3 = __ldg(&p3[(c0 + TPB * 3  ) * CH_ + 4]);
            acc = softplusf(v0) + softplusf(v1) + softplusf(v2) + softplusf(v3);
        } else if (o < OBJ_BLK0 + OBJ_BLK1) {
            const long c0 = (long)(o - OBJ_BLK0) * (TPB * 4) + tid;
            float v0 = __ldg(&p4[(c0            ) * CH_ + 4]);
            float v1 = __ldg(&p4[(c0 + TPB      ) * CH_ + 4]);
            float v2 = __ldg(&p4[(c0 + TPB * 2  ) * CH_ + 4]);
            float v3 = __ldg(&p4[(c0 + TPB * 3  ) * CH_ + 4]);
            acc = softplusf(v0) + softplusf(v1) + softplusf(v2) + softplusf(v3);
        } else {
            const long c0 = (long)(o - OBJ_BLK0 - OBJ_BLK1) * TPB + tid;
            acc = softplusf(__ldg(&p5[c0 * CH_ + 4]));
        }

        // block reduce -> one plain store to a distinct slot
        __shared__ float s_w[TPB / 32];
#pragma unroll
        for (int s = 16; s > 0; s >>= 1)
            acc += __shfl_down_sync(0xFFFFFFFFu, acc, s);
        if ((tid & 31) == 0) s_w[tid >> 5] = acc;
        __syncthreads();
        if (tid < 32) {
            float r = (tid < TPB / 32) ? s_w[tid] : 0.0f;
#pragma unroll
            for (int s = 4; s > 0; s >>= 1)
                r += __shfl_down_sync(0xFFFFFFFFu, r, s);
            if (tid == 0) g_part[blockIdx.x] = r;
        }
        return;
    }

    // ================= positives: one block per layer =======================
    __shared__ int    s_hash[HASH_SZ];
    __shared__ double s_cls, s_box, s_negx;
    __shared__ int    s_npos;

#pragma unroll
    for (int k = 0; k < HASH_SZ / TPB; k++) s_hash[k * TPB + tid] = -1;
    if (tid == 0) { s_cls = 0.0; s_box = 0.0; s_negx = 0.0; s_npos = 0; }
    __syncthreads();

    const int layer = blockIdx.x;
    const int g = 80 >> layer;
    const float gf = (float)g;
    const float* __restrict__ P = (layer == 0) ? p3 : (layer == 1) ? p4 : p5;
    const float aw0 = anchors[layer * 6 + 0], ah0 = anchors[layer * 6 + 1];
    const float aw1 = anchors[layer * 6 + 2], ah1 = anchors[layer * 6 + 3];
    const float aw2 = anchors[layer * 6 + 4], ah2 = anchors[layer * 6 + 5];

#pragma unroll
    for (int j = 0; j < NBOX / TPB; j++) {
        const int i = j * TPB + tid;        // box index b*M + m
        const int b = i >> 6;

        const float x1 = boxes[i * 4 + 0];
        const float y1 = boxes[i * 4 + 1];
        const float x2 = boxes[i * 4 + 2];
        const float y2 = boxes[i * 4 + 3];
        const float cx = (x1 + x2) * 0.5f * gf;
        const float cy = (y1 + y2) * 0.5f * gf;
        const float w  = (x2 - x1) * gf;
        const float h  = (y2 - y1) * gf;

        // wh-IoU vs 3 anchors; first-max argmax (strict >)
        const float wh = w * h;
        float best; int ba;
        {
            float in0 = fminf(w, aw0) * fminf(h, ah0);
            float i0  = in0 / (wh + aw0 * ah0 - in0 + 1e-6f);
            float in1 = fminf(w, aw1) * fminf(h, ah1);
            float i1  = in1 / (wh + aw1 * ah1 - in1 + 1e-6f);
            float in2 = fminf(w, aw2) * fminf(h, ah2);
            float i2  = in2 / (wh + aw2 * ah2 - in2 + 1e-6f);
            best = i0; ba = 0;
            if (i1 > best) { best = i1; ba = 1; }
            if (i2 > best) { best = i2; ba = 2; }
        }

        if (valid[i] && best > 0.5f) {
            int gx = (int)cx; gx = min(max(gx, 0), g - 1);
            int gy = (int)cy; gy = min(max(gy, 0), g - 1);
            const int  cell = ((b * A_ + ba) * g + gy) * g + gx;
            const long base = (long)cell * CH_;

            atomicAdd(&s_npos, 1);

            // ---- cls: sum_c softplus(x_c) - x_label ------------------------
            const int lab = labels[i];
            float cl = 0.0f;
#pragma unroll 4
            for (int c = 0; c < NC_; c++)
                cl += softplusf(__ldg(&P[base + 5 + c]));
            cl -= __ldg(&P[base + 5 + lab]);
            atomicAdd(&s_cls, (double)cl);

            // ---- bbox: CIoU loss (reference epsilons) ----------------------
            const float pcx0 = P[base + 0], pcy0 = P[base + 1];
            const float pw   = P[base + 2], ph   = P[base + 3];
            const float px1 = pcx0 - pw * 0.5f, py1 = pcy0 - ph * 0.5f;
            const float px2 = pcx0 + pw * 0.5f, py2 = pcy0 + ph * 0.5f;
            const float tx1 = cx - w * 0.5f, ty1 = cy - h * 0.5f;
            const float tx2 = cx + w * 0.5f, ty2 = cy + h * 0.5f;

            const float ix1 = fmaxf(px1, tx1), iy1 = fmaxf(py1, ty1);
            const float ix2 = fminf(px2, tx2), iy2 = fminf(py2, ty2);
            const float inter = fmaxf(ix2 - ix1, 0.0f) * fmaxf(iy2 - iy1, 0.0f);
            const float a1 = (px2 - px1) * (py2 - py1);
            const float a2 = (tx2 - tx1) * (ty2 - ty1);
            const float iou = inter / (a1 + a2 - inter + 1e-7f);

            const float pcx = (px1 + px2) * 0.5f, pcy = (py1 + py2) * 0.5f;
            const float tcx = (tx1 + tx2) * 0.5f, tcy = (ty1 + ty2) * 0.5f;
            const float cd  = (pcx - tcx) * (pcx - tcx) + (pcy - tcy) * (pcy - tcy);

            const float ex1 = fminf(px1, tx1), ey1 = fminf(py1, ty1);
            const float ex2 = fmaxf(px2, tx2), ey2 = fmaxf(py2, ty2);
            const float dd  = (ex2 - ex1) * (ex2 - ex1) + (ey2 - ey1) * (ey2 - ey1);

            atomicAdd(&s_box, (double)(1.0f - (iou - cd / (dd + 1e-7f))));

            // ---- dedup unique cells via smem hash --------------------------
            unsigned int hsh = (((unsigned int)cell * 2654435761u) >> 20) & (HASH_SZ - 1);
            bool owner = false;
            for (;;) {
                int old = atomicCAS(&s_hash[hsh], -1, cell);
                if (old == -1) { owner = true; break; }
                if (old == cell) break;
                hsh = (hsh + 1) & (HASH_SZ - 1);
            }
            if (owner) atomicAdd(&s_negx, -(double)P[base + 4]);
        }
    }
    __syncthreads();
    if (tid == 0) {
        g_cls[layer]  = s_cls;       // plain stores, always overwritten
        g_box[layer]  = s_box;
        g_negx[layer] = s_negx;
        g_npos[layer] = s_npos;
    }
}

// ---------------------------------------------------------------------------
// One block: sum 450 partials per layer (shared double atomics), combine.
__global__ void __launch_bounds__(512)
dl_fin_kernel(float* __restrict__ out) {
    __shared__ double s_sp[3];
    const int tid = threadIdx.x;
    if (tid < 3) s_sp[tid] = 0.0;
    __syncthreads();

    if (tid < OBJ_BLOCKS) {
        const float v = g_part[tid + 3];
        const int layer = (tid < OBJ_BLK0) ? 0
                        : (tid < OBJ_BLK0 + OBJ_BLK1) ? 1 : 2;
        atomicAdd(&s_sp[layer], (double)v);
    }
    __syncthreads();

    if (tid == 0) {
        const double ncell[3] = {(double)CELLS0, (double)CELLS1, (double)CELLS2};
        double cls = 0.0, obj = 0.0, box = 0.0;
#pragma unroll
        for (int l = 0; l < 3; l++) {
            const int np = g_npos[l];
            if (np > 0) {
                const double denom = (double)np;
                cls += g_cls[l] / (denom * (double)NC_);
                obj += (s_sp[l] + g_negx[l]) / ncell[l];
                box += g_box[l] / denom;
            }
        }
        out[0] = (float)(0.5 * cls + 1.0 * obj + 0.05 * box);
    }
}

// ---------------------------------------------------------------------------
extern "C" void kernel_launch(void* const* d_in, const int* in_sizes, int n_in,
                              void* d_out, int out_size) {
    const float*         p3      = (const float*)d_in[0];
    const float*         p4      = (const float*)d_in[1];
    const float*         p5      = (const float*)d_in[2];
    const float*         boxes   = (const float*)d_in[3];
    const int*           labels  = (const int*)d_in[4];
    const unsigned char* valid   = (const unsigned char*)d_in[5];
    const float*         anchors = (const float*)d_in[6];
    float*               out     = (float*)d_out;

    dl_main_kernel<<<TOTAL_BLOCKS, TPB>>>(p3, p4, p5, boxes, labels, valid,
                                          anchors);
    dl_fin_kernel<<<1, 512>>>(out);
}

// round 5
// speedup vs baseline: 3.9882x; 3.9882x over previous
#include <cuda_runtime.h>
#include <cuda_bf16.h>

// ---------------------------------------------------------------------------
// DetectionLoss (YOLOv5-style), two kernels, NO contended atomics anywhere.
//   p3 [16,3,80,80,85] p4 [16,3,40,40,85] p5 [16,3,20,20,85]
//   boxes [16,64,4] xyxy, labels [16,64] i32, valid [16,64] bool, anchors[3,3,2]
// Output: scalar f32.
//
// BCE(x,t) = softplus(x) - x*t  =>
//   obj_l = ( sum_all softplus(x4) - sum_{unique pos cells} x4 ) / Ncells_l
//
// Kernel 1 (462 blocks x 256):
//   blocks 0..11  : positives. block = layer*4 + quarter; 1 box/thread over 4
//                   batches; register accumulation + shuffle/smem TREE reduce;
//                   int-CAS smem hash for unique-cell dedup (cell id contains
//                   batch, so duplicates are block-local). Plain stores of 4
//                   partials per block.
//   blocks 12..461: obj softplus sweep, exact ranges (no bounds checks),
//                   4 independent loads/thread (1 for p5), tree reduce, plain
//                   store to g_obj[block].
// Kernel 2 (1 block x 512): segmented warp-shuffle double reduction of the
//   450 obj partials + fold of 12 pos partials; writes the scalar.
// All globals are fully overwritten every launch -> graph-replay safe.
// ---------------------------------------------------------------------------

#define B_    16
#define M_    64
#define A_    3
#define NC_   80
#define CH_   85
#define NBOX  (B_ * M_)               // 1024
#define CELLS0 (B_ * A_ * 80 * 80)    // 307200
#define CELLS1 (B_ * A_ * 40 * 40)    // 76800
#define CELLS2 (B_ * A_ * 20 * 20)    // 19200

#define TPB 256
#define POS_BLOCKS 12
#define OBJ_BLK0 (CELLS0 / (TPB * 4))   // 300
#define OBJ_BLK1 (CELLS1 / (TPB * 4))   // 75
#define OBJ_BLK2 (CELLS2 / TPB)         // 75
#define OBJ_BLOCKS (OBJ_BLK0 + OBJ_BLK1 + OBJ_BLK2)   // 450
#define TOTAL_BLOCKS (POS_BLOCKS + OBJ_BLOCKS)        // 462
#define HASH_SZ 512

static __device__ float g_obj[OBJ_BLOCKS];   // obj softplus partial per block
static __device__ float g_pcls[POS_BLOCKS];
static __device__ float g_pbox[POS_BLOCKS];
static __device__ float g_pngx[POS_BLOCKS];
static __device__ int   g_pnp [POS_BLOCKS];

__device__ __forceinline__ float softplusf(float x) {
    return fmaxf(x, 0.0f) + log1pf(expf(-fabsf(x)));
}

// ---------------------------------------------------------------------------
__global__ void __launch_bounds__(TPB)
dl_main_kernel(const float* __restrict__ p3,
               const float* __restrict__ p4,
               const float* __restrict__ p5,
               const float* __restrict__ boxes,
               const int*   __restrict__ labels,
               const unsigned char* __restrict__ valid,
               const float* __restrict__ anchors) {
    const int tid = threadIdx.x;

    if (blockIdx.x >= POS_BLOCKS) {
        // ============== obj softplus sweep: exact ranges, no checks =========
        const int o = blockIdx.x - POS_BLOCKS;
        float acc;
        if (o < OBJ_BLK0) {
            const long c0 = (long)o * (TPB * 4) + tid;
            float v0 = __ldg(&p3[(c0          ) * CH_ + 4]);
            float v1 = __ldg(&p3[(c0 + TPB    ) * CH_ + 4]);
            float v2 = __ldg(&p3[(c0 + TPB * 2) * CH_ + 4]);
            float v3 = __ldg(&p3[(c0 + TPB * 3) * CH_ + 4]);
            acc = softplusf(v0) + softplusf(v1) + softplusf(v2) + softplusf(v3);
        } else if (o < OBJ_BLK0 + OBJ_BLK1) {
            const long c0 = (long)(o - OBJ_BLK0) * (TPB * 4) + tid;
            float v0 = __ldg(&p4[(c0          ) * CH_ + 4]);
            float v1 = __ldg(&p4[(c0 + TPB    ) * CH_ + 4]);
            float v2 = __ldg(&p4[(c0 + TPB * 2) * CH_ + 4]);
            float v3 = __ldg(&p4[(c0 + TPB * 3) * CH_ + 4]);
            acc = softplusf(v0) + softplusf(v1) + softplusf(v2) + softplusf(v3);
        } else {
            const long c0 = (long)(o - OBJ_BLK0 - OBJ_BLK1) * TPB + tid;
            acc = softplusf(__ldg(&p5[c0 * CH_ + 4]));
        }

        __shared__ float s_w[TPB / 32];
#pragma unroll
        for (int s = 16; s > 0; s >>= 1)
            acc += __shfl_down_sync(0xFFFFFFFFu, acc, s);
        if ((tid & 31) == 0) s_w[tid >> 5] = acc;
        __syncthreads();
        if (tid < 32) {
            float r = (tid < TPB / 32) ? s_w[tid] : 0.0f;
#pragma unroll
            for (int s = 4; s > 0; s >>= 1)
                r += __shfl_down_sync(0xFFFFFFFFu, r, s);
            if (tid == 0) g_obj[o] = r;
        }
        return;
    }

    // ================= positives: 4 blocks per layer, 1 box/thread ==========
    __shared__ int   s_hash[HASH_SZ];
    __shared__ float s_rc[TPB / 32], s_rb[TPB / 32], s_rn[TPB / 32];
    __shared__ int   s_rp[TPB / 32];

#pragma unroll
    for (int k = 0; k < HASH_SZ / TPB; k++) s_hash[k * TPB + tid] = -1;
    __syncthreads();

    const int layer   = blockIdx.x >> 2;
    const int quarter = blockIdx.x & 3;
    const int i = quarter * TPB + tid;     // box index b*M + m
    const int b = i >> 6;
    const int g = 80 >> layer;
    const float gf = (float)g;
    const float* __restrict__ P = (layer == 0) ? p3 : (layer == 1) ? p4 : p5;
    const float aw0 = __ldg(&anchors[layer * 6 + 0]), ah0 = __ldg(&anchors[layer * 6 + 1]);
    const float aw1 = __ldg(&anchors[layer * 6 + 2]), ah1 = __ldg(&anchors[layer * 6 + 3]);
    const float aw2 = __ldg(&anchors[layer * 6 + 4]), ah2 = __ldg(&anchors[layer * 6 + 5]);

    const float x1 = boxes[i * 4 + 0];
    const float y1 = boxes[i * 4 + 1];
    const float x2 = boxes[i * 4 + 2];
    const float y2 = boxes[i * 4 + 3];
    const float cx = (x1 + x2) * 0.5f * gf;
    const float cy = (y1 + y2) * 0.5f * gf;
    const float w  = (x2 - x1) * gf;
    const float h  = (y2 - y1) * gf;

    // wh-IoU vs 3 anchors; first-max argmax (strict >)
    const float wh = w * h;
    float best; int ba;
    {
        float in0 = fminf(w, aw0) * fminf(h, ah0);
        float i0  = in0 / (wh + aw0 * ah0 - in0 + 1e-6f);
        float in1 = fminf(w, aw1) * fminf(h, ah1);
        float i1  = in1 / (wh + aw1 * ah1 - in1 + 1e-6f);
        float in2 = fminf(w, aw2) * fminf(h, ah2);
        float i2  = in2 / (wh + aw2 * ah2 - in2 + 1e-6f);
        best = i0; ba = 0;
        if (i1 > best) { best = i1; ba = 1; }
        if (i2 > best) { best = i2; ba = 2; }
    }

    float cls_acc = 0.0f, box_acc = 0.0f, ngx_acc = 0.0f;
    int   np = 0;

    if (valid[i] && best > 0.5f) {
        int gx = (int)cx; gx = min(max(gx, 0), g - 1);
        int gy = (int)cy; gy = min(max(gy, 0), g - 1);
        const int  cell = ((b * A_ + ba) * g + gy) * g + gx;
        const long base = (long)cell * CH_;

        np = 1;

        // ---- cls: sum_c softplus(x_c) - x_label ----------------------------
        const int lab = labels[i];
        float cl = 0.0f;
#pragma unroll 4
        for (int c = 0; c < NC_; c++)
            cl += softplusf(__ldg(&P[base + 5 + c]));
        cl -= __ldg(&P[base + 5 + lab]);
        cls_acc = cl;

        // ---- bbox: CIoU loss (reference epsilons) --------------------------
        const float pcx0 = P[base + 0], pcy0 = P[base + 1];
        const float pw   = P[base + 2], ph   = P[base + 3];
        const float px1 = pcx0 - pw * 0.5f, py1 = pcy0 - ph * 0.5f;
        const float px2 = pcx0 + pw * 0.5f, py2 = pcy0 + ph * 0.5f;
        const float tx1 = cx - w * 0.5f, ty1 = cy - h * 0.5f;
        const float tx2 = cx + w * 0.5f, ty2 = cy + h * 0.5f;

        const float ix1 = fmaxf(px1, tx1), iy1 = fmaxf(py1, ty1);
        const float ix2 = fminf(px2, tx2), iy2 = fminf(py2, ty2);
        const float inter = fmaxf(ix2 - ix1, 0.0f) * fmaxf(iy2 - iy1, 0.0f);
        const float a1 = (px2 - px1) * (py2 - py1);
        const float a2 = (tx2 - tx1) * (ty2 - ty1);
        const float iou = inter / (a1 + a2 - inter + 1e-7f);

        const float pcx = (px1 + px2) * 0.5f, pcy = (py1 + py2) * 0.5f;
        const float tcx = (tx1 + tx2) * 0.5f, tcy = (ty1 + ty2) * 0.5f;
        const float cd  = (pcx - tcx) * (pcx - tcx) + (pcy - tcy) * (pcy - tcy);

        const float ex1 = fminf(px1, tx1), ey1 = fminf(py1, ty1);
        const float ex2 = fmaxf(px2, tx2), ey2 = fmaxf(py2, ty2);
        const float dd  = (ex2 - ex1) * (ex2 - ex1) + (ey2 - ey1) * (ey2 - ey1);

        box_acc = 1.0f - (iou - cd / (dd + 1e-7f));

        // ---- dedup unique cells via int smem hash (cheap, sparse) ----------
        unsigned int hsh = (((unsigned int)cell * 2654435761u) >> 23) & (HASH_SZ - 1);
        bool owner = false;
        for (;;) {
            int old = atomicCAS(&s_hash[hsh], -1, cell);
            if (old == -1) { owner = true; break; }
            if (old == cell) break;
            hsh = (hsh + 1) & (HASH_SZ - 1);
        }
        if (owner) ngx_acc = -P[base + 4];
    }

    // ---- block tree reduction (no atomics) ---------------------------------
#pragma unroll
    for (int s = 16; s > 0; s >>= 1) {
        cls_acc += __shfl_down_sync(0xFFFFFFFFu, cls_acc, s);
        box_acc += __shfl_down_sync(0xFFFFFFFFu, box_acc, s);
        ngx_acc += __shfl_down_sync(0xFFFFFFFFu, ngx_acc, s);
        np      += __shfl_down_sync(0xFFFFFFFFu, np, s);
    }
    if ((tid & 31) == 0) {
        s_rc[tid >> 5] = cls_acc;
        s_rb[tid >> 5] = box_acc;
        s_rn[tid >> 5] = ngx_acc;
        s_rp[tid >> 5] = np;
    }
    __syncthreads();
    if (tid < 32) {
        float rc = (tid < TPB / 32) ? s_rc[tid] : 0.0f;
        float rb = (tid < TPB / 32) ? s_rb[tid] : 0.0f;
        float rn = (tid < TPB / 32) ? s_rn[tid] : 0.0f;
        int   rp = (tid < TPB / 32) ? s_rp[tid] : 0;
#pragma unroll
        for (int s = 4; s > 0; s >>= 1) {
            rc += __shfl_down_sync(0xFFFFFFFFu, rc, s);
            rb += __shfl_down_sync(0xFFFFFFFFu, rb, s);
            rn += __shfl_down_sync(0xFFFFFFFFu, rn, s);
            rp += __shfl_down_sync(0xFFFFFFFFu, rp, s);
        }
        if (tid == 0) {
            g_pcls[blockIdx.x] = rc;
            g_pbox[blockIdx.x] = rb;
            g_pngx[blockIdx.x] = rn;
            g_pnp [blockIdx.x] = rp;
        }
    }
}

// ---------------------------------------------------------------------------
// One block, 512 threads. Warps 0-7 -> layer0 obj partials (300), warps 8-11
// -> layer1 (75), warps 12-15 -> layer2 (75). Double shuffle reduction.
__global__ void __launch_bounds__(512)
dl_fin_kernel(float* __restrict__ out) {
    __shared__ double s_red[16];
    const int tid = threadIdx.x;
    const int w = tid >> 5;

    double acc = 0.0;
    if (w < 8) {                       // layer 0: entries 0..299
        acc = (double)g_obj[tid];
        if (tid < OBJ_BLK0 - 256) acc += (double)g_obj[tid + 256];
    } else if (w < 12) {               // layer 1: entries 300..374
        const int t = tid - 256;
        if (t < OBJ_BLK1) acc = (double)g_obj[OBJ_BLK0 + t];
    } else {                           // layer 2: entries 375..449
        const int t = tid - 384;
        if (t < OBJ_BLK2) acc = (double)g_obj[OBJ_BLK0 + OBJ_BLK1 + t];
    }
#pragma unroll
    for (int s = 16; s > 0; s >>= 1)
        acc += __shfl_down_sync(0xFFFFFFFFu, acc, s);
    if ((tid & 31) == 0) s_red[w] = acc;
    __syncthreads();

    if (tid == 0) {
        double sp[3];
        sp[0] = ((s_red[0] + s_red[1]) + (s_red[2] + s_red[3]))
              + ((s_red[4] + s_red[5]) + (s_red[6] + s_red[7]));
        sp[1] = (s_red[8] + s_red[9]) + (s_red[10] + s_red[11]);
        sp[2] = (s_red[12] + s_red[13]) + (s_red[14] + s_red[15]);

        const double ncell[3] = {(double)CELLS0, (double)CELLS1, (double)CELLS2};
        double cls = 0.0, obj = 0.0, box = 0.0;
#pragma unroll
        for (int l = 0; l < 3; l++) {
            double pc = 0.0, pb = 0.0, pn = 0.0;
            int np = 0;
#pragma unroll
            for (int q = 0; q < 4; q++) {
                pc += (double)g_pcls[l * 4 + q];
                pb += (double)g_pbox[l * 4 + q];
                pn += (double)g_pngx[l * 4 + q];
                np += g_pnp[l * 4 + q];
            }
            if (np > 0) {
                const double denom = (double)np;
                cls += pc / (denom * (double)NC_);
                obj += (sp[l] + pn) / ncell[l];
                box += pb / denom;
            }
        }
        out[0] = (float)(0.5 * cls + 1.0 * obj + 0.05 * box);
    }
}

// ---------------------------------------------------------------------------
extern "C" void kernel_launch(void* const* d_in, const int* in_sizes, int n_in,
                              void* d_out, int out_size) {
    const float*         p3      = (const float*)d_in[0];
    const float*         p4      = (const float*)d_in[1];
    const float*         p5      = (const float*)d_in[2];
    const float*         boxes   = (const float*)d_in[3];
    const int*           labels  = (const int*)d_in[4];
    const unsigned char* valid   = (const unsigned char*)d_in[5];
    const float*         anchors = (const float*)d_in[6];
    float*               out     = (float*)d_out;

    dl_main_kernel<<<TOTAL_BLOCKS, TPB>>>(p3, p4, p5, boxes, labels, valid,
                                          anchors);
    dl_fin_kernel<<<1, 512>>>(out);
}